// round 3
// baseline (speedup 1.0000x reference)
#include <cuda_runtime.h>
#include <cuda_bf16.h>

typedef __nv_bfloat16 bf16;

#define NT 512
#define TILES 8192      // B(2) * 64 * 64
#define GRP 4           // tiles per CTA (64%4==0 -> never wraps a tile row) -> 100 rows, pad 128
#define SA 264          // A row stride (bf16): 132 words == 4 mod 32 -> conflict-free frags
#define SE 136          // Epi row stride (bf16): 68 words == 4 mod 32
#define SO 133          // outs row stride (fp32): == 5 mod 32
#define SX 101          // xt channel stride (fp32 words): == 5 mod 32

// ---------------- precomputed combined weights (bf16) ----------------
__device__ __align__(16) bf16 g_Wc[128 * 256];    // [o][k]: k<128 = Wfuse_h@Whpw, k>=128 = Wfuse_v@Wvpw
__device__ __align__(16) bf16 g_Wdm1[32 * 128];
__device__ __align__(16) bf16 g_Wdm2[128 * 32];

__global__ void prep_kernel(const float* __restrict__ whpw, const float* __restrict__ wvpw,
                            const float* __restrict__ wdm1, const float* __restrict__ wdm2,
                            const float* __restrict__ wfuse) {
  int o = blockIdx.x, c = threadIdx.x;
  float sh = 0.f, sv = 0.f;
  for (int m = 0; m < 128; ++m) {
    sh += wfuse[o * 256 + m]       * whpw[m * 128 + c];
    sv += wfuse[o * 256 + 128 + m] * wvpw[m * 128 + c];
  }
  g_Wc[o * 256 + c]       = __float2bfloat16(sh);
  g_Wc[o * 256 + 128 + c] = __float2bfloat16(sv);
  if (o < 32) g_Wdm1[o * 128 + c] = __float2bfloat16(wdm1[o * 128 + c]);
  if (c < 32) g_Wdm2[o * 32 + c]  = __float2bfloat16(wdm2[o * 32 + c]);
}

// ---------------- helpers ----------------
__device__ __forceinline__ void mma16816(float* d, const unsigned* a, unsigned b0, unsigned b1) {
  asm volatile(
      "mma.sync.aligned.m16n8k16.row.col.f32.bf16.bf16.f32 "
      "{%0,%1,%2,%3}, {%4,%5,%6,%7}, {%8,%9}, {%0,%1,%2,%3};\n"
      : "+f"(d[0]), "+f"(d[1]), "+f"(d[2]), "+f"(d[3])
      : "r"(a[0]), "r"(a[1]), "r"(a[2]), "r"(a[3]), "r"(b0), "r"(b1));
}
__device__ __forceinline__ unsigned pack2(float a, float b) {
  unsigned lo = (unsigned)__bfloat16_as_ushort(__float2bfloat16(a));
  unsigned hi = (unsigned)__bfloat16_as_ushort(__float2bfloat16(b));
  return lo | (hi << 16);
}
__device__ __forceinline__ float lo2f(unsigned u) {
  return __bfloat162float(__ushort_as_bfloat16((unsigned short)(u & 0xffffu)));
}
__device__ __forceinline__ float hi2f(unsigned u) {
  return __bfloat162float(__ushort_as_bfloat16((unsigned short)(u >> 16)));
}
__device__ __forceinline__ float lrelu(float x) { return x > 0.f ? x : 0.1f * x; }
__device__ __forceinline__ float sigmoidf_(float x) { return 1.0f / (1.0f + expf(-x)); }

// ---------------- smem layout (bytes) ----------------
// region 0 (union): A bf16 [128][SA] (67584)  |  outs fp32 [128][SO] (68096)
#define OFF_A     0
#define OFF_OUTS  0
// region 1: xt fp32 [128][SX] (alive phase 1a -> phase 5)
#define OFF_XT    68096
// region 2: Epi bf16 [128][SE]
#define OFF_EPI   119808
// region 3: Hid bf16 [128][40]
#define OFF_HID   154624
#define SMEM_TOTAL 164864

__global__ __launch_bounds__(NT, 1)
void epi_kernel(const float* __restrict__ x,
                const float* __restrict__ whdw, const float* __restrict__ wvdw,
                const float* __restrict__ scale,
                float* __restrict__ out) {
  extern __shared__ char smem[];
  bf16*  A    = (bf16*)(smem + OFF_A);      // [128][SA]  (cols 0..127 = ah, 128..255 = av)
  float* outs = (float*)(smem + OFF_OUTS);  // [128][SO]
  float* xt   = (float*)(smem + OFF_XT);    // [c][u][20], stride SX per channel
  bf16*  Epi  = (bf16*)(smem + OFF_EPI);    // [128][SE]
  bf16*  Hid  = (bf16*)(smem + OFF_HID);    // [128][40]

  const int tid  = threadIdx.x;
  const int wid  = tid >> 5;
  const int lane = tid & 31;
  const int g    = lane >> 2;
  const int tg   = lane & 3;

  const int t0 = blockIdx.x * GRP;
  const int b  = t0 >> 12, hh = (t0 >> 6) & 63, ww0 = t0 & 63;
  const int base0 = b * 13107200 + hh * 1600 + ww0 * 5;

  // ---------- Phase 1a: flat coalesced load of 4 tiles (20-float runs) ----------
  // f -> c = f/100, r = f%100, u = r/20, j = r%20;  global col = ww0*5 + j
  #pragma unroll 5
  for (int f = tid; f < 12800; f += NT) {
    int c = f / 100, r = f - c * 100;
    int u = r / 20, j = r - u * 20;
    xt[c * SX + u * 20 + j] = x[base0 + c * 102400 + u * 320 + j];
  }
  // zero A pad rows (100..127)
  {
    unsigned* A32 = (unsigned*)(A + 100 * SA);
    for (int f = tid; f < 28 * (SA / 2); f += NT) A32[f] = 0u;
  }
  __syncthreads();

  // ---------- Phase 1b: depthwise conv + lrelu -> A (one (tile,channel) per thread) ----------
  {
    int i = tid >> 7, c = tid & 127;
    float xr[25];
    const float* xp = xt + c * SX + i * 5;   // xr[u*5+v] = xp[u*20 + v]
    #pragma unroll
    for (int u = 0; u < 5; ++u)
      #pragma unroll
      for (int v = 0; v < 5; ++v) xr[u * 5 + v] = xp[u * 20 + v];
    float wh[5], wv[5];
    #pragma unroll
    for (int j = 0; j < 5; ++j) { wh[j] = whdw[c * 5 + j]; wv[j] = wvdw[c * 5 + j]; }
    bf16* Ar = A + (i * 25) * SA + c;
    #pragma unroll
    for (int u = 0; u < 5; ++u) {
      #pragma unroll
      for (int v = 0; v < 5; ++v) {
        float ah = wh[2] * xr[u * 5 + v];
        float av = wv[2] * xr[u * 5 + v];
        if (v >= 1) ah += wh[1] * xr[u * 5 + v - 1];
        if (v >= 2) ah += wh[0] * xr[u * 5 + v - 2];
        if (v <= 3) ah += wh[3] * xr[u * 5 + v + 1];
        if (v <= 2) ah += wh[4] * xr[u * 5 + v + 2];
        if (u >= 1) av += wv[1] * xr[(u - 1) * 5 + v];
        if (u >= 2) av += wv[0] * xr[(u - 2) * 5 + v];
        if (u <= 3) av += wv[3] * xr[(u + 1) * 5 + v];
        if (u <= 2) av += wv[4] * xr[(u + 2) * 5 + v];
        int q = u * 5 + v;
        Ar[q * SA]       = __float2bfloat16(lrelu(ah));
        Ar[q * SA + 128] = __float2bfloat16(lrelu(av));
      }
    }
  }
  __syncthreads();

  // ---------- Phase 2: epi = A @ Wc^T (M128 N128 K256); B frags straight from global (L1-hot) ----------
  const int wm = wid >> 2;
  const int wn = wid & 3;
  float acc[2][4][4];
  #pragma unroll
  for (int a = 0; a < 2; ++a)
    #pragma unroll
    for (int b2 = 0; b2 < 4; ++b2)
      #pragma unroll
      for (int c2 = 0; c2 < 4; ++c2) acc[a][b2][c2] = 0.f;

  #pragma unroll
  for (int kk = 0; kk < 16; ++kk) {
    int k0 = kk * 16;
    unsigned afr[2][4];
    #pragma unroll
    for (int mi = 0; mi < 2; ++mi) {
      int r = wm * 32 + mi * 16 + g;
      afr[mi][0] = *(const unsigned*)(A + r * SA + k0 + tg * 2);
      afr[mi][1] = *(const unsigned*)(A + (r + 8) * SA + k0 + tg * 2);
      afr[mi][2] = *(const unsigned*)(A + r * SA + k0 + 8 + tg * 2);
      afr[mi][3] = *(const unsigned*)(A + (r + 8) * SA + k0 + 8 + tg * 2);
    }
    #pragma unroll
    for (int ni = 0; ni < 4; ++ni) {
      int n = wn * 32 + ni * 8 + g;
      unsigned b0 = *(const unsigned*)(g_Wc + n * 256 + k0 + tg * 2);
      unsigned b1 = *(const unsigned*)(g_Wc + n * 256 + k0 + 8 + tg * 2);
      mma16816(acc[0][ni], afr[0], b0, b1);
      mma16816(acc[1][ni], afr[1], b0, b1);
    }
  }
  // pack epi to bf16 regs + store to smem for phase 3
  unsigned epk[2][4][2];
  #pragma unroll
  for (int mi = 0; mi < 2; ++mi)
    #pragma unroll
    for (int ni = 0; ni < 4; ++ni) {
      epk[mi][ni][0] = pack2(acc[mi][ni][0], acc[mi][ni][1]);
      epk[mi][ni][1] = pack2(acc[mi][ni][2], acc[mi][ni][3]);
      int r  = wm * 32 + mi * 16 + g;
      int c0 = wn * 32 + ni * 8 + tg * 2;
      *(unsigned*)(Epi + r * SE + c0)       = epk[mi][ni][0];
      *(unsigned*)(Epi + (r + 8) * SE + c0) = epk[mi][ni][1];
    }
  __syncthreads();

  // ---------- Phase 3: hid = lrelu(epi @ Wdm1^T) (M128 N32 K128), warps 0..7 ----------
  if (wid < 8) {
    int rb = wid * 16;
    float hacc[4][4];
    #pragma unroll
    for (int a = 0; a < 4; ++a)
      #pragma unroll
      for (int b2 = 0; b2 < 4; ++b2) hacc[a][b2] = 0.f;
    #pragma unroll
    for (int kk = 0; kk < 8; ++kk) {
      int k0 = kk * 16;
      unsigned afr[4];
      int r = rb + g;
      afr[0] = *(const unsigned*)(Epi + r * SE + k0 + tg * 2);
      afr[1] = *(const unsigned*)(Epi + (r + 8) * SE + k0 + tg * 2);
      afr[2] = *(const unsigned*)(Epi + r * SE + k0 + 8 + tg * 2);
      afr[3] = *(const unsigned*)(Epi + (r + 8) * SE + k0 + 8 + tg * 2);
      #pragma unroll
      for (int ni = 0; ni < 4; ++ni) {
        int n = ni * 8 + g;
        unsigned b0 = *(const unsigned*)(g_Wdm1 + n * 128 + k0 + tg * 2);
        unsigned b1 = *(const unsigned*)(g_Wdm1 + n * 128 + k0 + 8 + tg * 2);
        mma16816(hacc[ni], afr, b0, b1);
      }
    }
    #pragma unroll
    for (int ni = 0; ni < 4; ++ni) {
      int r = rb + g, c0 = ni * 8 + tg * 2;
      *(unsigned*)(Hid + r * 40 + c0)       = pack2(lrelu(hacc[ni][0]), lrelu(hacc[ni][1]));
      *(unsigned*)(Hid + (r + 8) * 40 + c0) = pack2(lrelu(hacc[ni][2]), lrelu(hacc[ni][3]));
    }
  }
  __syncthreads();

  // ---------- Phase 4: dwgt = sigmoid(hid @ Wdm2^T); outs = scale*epi*dwgt ----------
  {
    float dacc[2][4][4];
    #pragma unroll
    for (int a = 0; a < 2; ++a)
      #pragma unroll
      for (int b2 = 0; b2 < 4; ++b2)
        #pragma unroll
        for (int c2 = 0; c2 < 4; ++c2) dacc[a][b2][c2] = 0.f;

    #pragma unroll
    for (int kk = 0; kk < 2; ++kk) {
      int k0 = kk * 16;
      unsigned afr[2][4];
      #pragma unroll
      for (int mi = 0; mi < 2; ++mi) {
        int r = wm * 32 + mi * 16 + g;
        afr[mi][0] = *(const unsigned*)(Hid + r * 40 + k0 + tg * 2);
        afr[mi][1] = *(const unsigned*)(Hid + (r + 8) * 40 + k0 + tg * 2);
        afr[mi][2] = *(const unsigned*)(Hid + r * 40 + k0 + 8 + tg * 2);
        afr[mi][3] = *(const unsigned*)(Hid + (r + 8) * 40 + k0 + 8 + tg * 2);
      }
      #pragma unroll
      for (int ni = 0; ni < 4; ++ni) {
        int n = wn * 32 + ni * 8 + g;
        unsigned b0 = *(const unsigned*)(g_Wdm2 + n * 32 + k0 + tg * 2);
        unsigned b1 = *(const unsigned*)(g_Wdm2 + n * 32 + k0 + 8 + tg * 2);
        mma16816(dacc[0][ni], afr[0], b0, b1);
        mma16816(dacc[1][ni], afr[1], b0, b1);
      }
    }
    float sc = scale[0];
    #pragma unroll
    for (int mi = 0; mi < 2; ++mi)
      #pragma unroll
      for (int ni = 0; ni < 4; ++ni) {
        int r  = wm * 32 + mi * 16 + g;
        int c0 = wn * 32 + ni * 8 + tg * 2;
        unsigned e01 = epk[mi][ni][0], e23 = epk[mi][ni][1];
        outs[r * SO + c0]           = sc * lo2f(e01) * sigmoidf_(dacc[mi][ni][0]);
        outs[r * SO + c0 + 1]       = sc * hi2f(e01) * sigmoidf_(dacc[mi][ni][1]);
        outs[(r + 8) * SO + c0]     = sc * lo2f(e23) * sigmoidf_(dacc[mi][ni][2]);
        outs[(r + 8) * SO + c0 + 1] = sc * hi2f(e23) * sigmoidf_(dacc[mi][ni][3]);
      }
  }
  __syncthreads();

  // ---------- Phase 5: out = xt + outs, coalesced 20-float runs, x NOT re-read from global ----------
  #pragma unroll 5
  for (int f = tid; f < 12800; f += NT) {
    int c = f / 100, r = f - c * 100;
    int u = r / 20, j = r - u * 20;
    int i = j / 5, v = j - i * 5;
    int row = i * 25 + u * 5 + v;
    out[base0 + c * 102400 + u * 320 + j] = xt[c * SX + u * 20 + j] + outs[row * SO + c];
  }
}

extern "C" void kernel_launch(void* const* d_in, const int* in_sizes, int n_in,
                              void* d_out, int out_size) {
  const float* x     = (const float*)d_in[0];
  const float* whdw  = (const float*)d_in[1];
  const float* whpw  = (const float*)d_in[2];
  const float* wvdw  = (const float*)d_in[3];
  const float* wvpw  = (const float*)d_in[4];
  const float* wdm1  = (const float*)d_in[5];
  const float* wdm2  = (const float*)d_in[6];
  const float* wfuse = (const float*)d_in[7];
  const float* scale = (const float*)d_in[8];
  float* out = (float*)d_out;

  prep_kernel<<<128, 128>>>(whpw, wvpw, wdm1, wdm2, wfuse);

  cudaFuncSetAttribute(epi_kernel, cudaFuncAttributeMaxDynamicSharedMemorySize, SMEM_TOTAL);
  epi_kernel<<<TILES / GRP, NT, SMEM_TOTAL>>>(x, whdw, wvdw, scale, out);
}

// round 4
// speedup vs baseline: 1.4519x; 1.4519x over previous
#include <cuda_runtime.h>
#include <cuda_bf16.h>

typedef __nv_bfloat16 bf16;

#define NT 512
#define TILES 8192      // B(2) * 64 * 64
#define GRP 4           // tiles per CTA (64%4==0 -> 20-float contiguous runs) -> 100 rows, pad 128
#define SA 264          // A row stride (bf16): 132 words == 4 mod 32 -> conflict-free frags
#define SE 136          // Epi row stride (bf16): 68 words == 4 mod 32
#define SO 133          // outs row stride (fp32): == 5 mod 32
#define SX 101          // xt channel stride (fp32 words): == 5 mod 32

// ---------------- precomputed combined weights (bf16) ----------------
__device__ __align__(16) bf16 g_Wc[128 * 256];    // [o][k]: k<128 = Wfuse_h@Whpw, k>=128 = Wfuse_v@Wvpw
__device__ __align__(16) bf16 g_Wdm1[32 * 128];
__device__ __align__(16) bf16 g_Wdm2[128 * 32];

__global__ void prep_kernel(const float* __restrict__ whpw, const float* __restrict__ wvpw,
                            const float* __restrict__ wdm1, const float* __restrict__ wdm2,
                            const float* __restrict__ wfuse) {
  int o = blockIdx.x, c = threadIdx.x;
  float sh = 0.f, sv = 0.f;
  for (int m = 0; m < 128; ++m) {
    sh += wfuse[o * 256 + m]       * whpw[m * 128 + c];
    sv += wfuse[o * 256 + 128 + m] * wvpw[m * 128 + c];
  }
  g_Wc[o * 256 + c]       = __float2bfloat16(sh);
  g_Wc[o * 256 + 128 + c] = __float2bfloat16(sv);
  if (o < 32) g_Wdm1[o * 128 + c] = __float2bfloat16(wdm1[o * 128 + c]);
  if (c < 32) g_Wdm2[o * 32 + c]  = __float2bfloat16(wdm2[o * 32 + c]);
}

// ---------------- helpers ----------------
__device__ __forceinline__ void mma16816(float* d, const unsigned* a, unsigned b0, unsigned b1) {
  asm volatile(
      "mma.sync.aligned.m16n8k16.row.col.f32.bf16.bf16.f32 "
      "{%0,%1,%2,%3}, {%4,%5,%6,%7}, {%8,%9}, {%0,%1,%2,%3};\n"
      : "+f"(d[0]), "+f"(d[1]), "+f"(d[2]), "+f"(d[3])
      : "r"(a[0]), "r"(a[1]), "r"(a[2]), "r"(a[3]), "r"(b0), "r"(b1));
}
__device__ __forceinline__ unsigned pack2(float a, float b) {
  unsigned lo = (unsigned)__bfloat16_as_ushort(__float2bfloat16(a));
  unsigned hi = (unsigned)__bfloat16_as_ushort(__float2bfloat16(b));
  return lo | (hi << 16);
}
__device__ __forceinline__ float lo2f(unsigned u) {
  return __bfloat162float(__ushort_as_bfloat16((unsigned short)(u & 0xffffu)));
}
__device__ __forceinline__ float hi2f(unsigned u) {
  return __bfloat162float(__ushort_as_bfloat16((unsigned short)(u >> 16)));
}
__device__ __forceinline__ float lrelu(float x) { return x > 0.f ? x : 0.1f * x; }
__device__ __forceinline__ float sigmoidf_(float x) { return 1.0f / (1.0f + expf(-x)); }

// ---------------- smem layout (bytes) ----------------
// region 0, time-multiplexed: A bf16[128][SA] (67584, ph1-2) -> Epi bf16[128][SE] (34816, ph2-3)
//                             -> outs fp32[128][SO] (68096, ph4-5)
#define OFF_A     0
#define OFF_EPI   0
#define OFF_OUTS  0
// region 1: Wc bf16 [128][SA]
#define OFF_WC    68096
// region 2: xt fp32 [128][SX] (alive phase 1a -> phase 5)
#define OFF_XT    135680
// region 3: Wdm1 bf16 [32][SE]
#define OFF_WDM1  187392
// region 4: Wdm2 bf16 [128][40]
#define OFF_WDM2  196096
// region 5: Hid bf16 [128][40]
#define OFF_HID   206336
// region 6: dw weights fp32 [2][640]
#define OFF_DWW   216576
#define SMEM_TOTAL 221696

__global__ __launch_bounds__(NT, 1)
void epi_kernel(const float* __restrict__ x,
                const float* __restrict__ whdw, const float* __restrict__ wvdw,
                const float* __restrict__ scale,
                float* __restrict__ out) {
  extern __shared__ char smem[];
  bf16*  A      = (bf16*)(smem + OFF_A);      // [128][SA]  (cols 0..127 = ah, 128..255 = av)
  bf16*  Epi    = (bf16*)(smem + OFF_EPI);    // [128][SE]
  float* outs   = (float*)(smem + OFF_OUTS);  // [128][SO]
  bf16*  Wc_s   = (bf16*)(smem + OFF_WC);     // [128][SA]
  float* xt     = (float*)(smem + OFF_XT);    // [c][u][20], stride SX per channel
  bf16*  Wdm1_s = (bf16*)(smem + OFF_WDM1);   // [32][SE]
  bf16*  Wdm2_s = (bf16*)(smem + OFF_WDM2);   // [128][40]
  bf16*  Hid    = (bf16*)(smem + OFF_HID);    // [128][40]
  float* whdw_s = (float*)(smem + OFF_DWW);   // [640]
  float* wvdw_s = (float*)(smem + OFF_DWW + 2560);

  const int tid  = threadIdx.x;
  const int wid  = tid >> 5;
  const int lane = tid & 31;
  const int g    = lane >> 2;
  const int tg   = lane & 3;

  const int t0 = blockIdx.x * GRP;
  const int b  = t0 >> 12, hh = (t0 >> 6) & 63, ww0 = t0 & 63;
  const int base0 = b * 13107200 + hh * 1600 + ww0 * 5;

  // ---------- Phase 0: stage ALL weights into smem (overlaps phase-1a LDGs) ----------
  {
    const uint4* src = (const uint4*)g_Wc;
    for (int f = tid; f < 4096; f += NT) {          // 128 rows * 32 uint4
      int n = f >> 5, k8 = (f & 31) << 3;
      *(uint4*)(Wc_s + n * SA + k8) = src[f];
    }
    const uint4* s1 = (const uint4*)g_Wdm1;
    for (int f = tid; f < 512; f += NT) {           // 32*128/8
      int n = f >> 4, k8 = (f & 15) << 3;
      *(uint4*)(Wdm1_s + n * SE + k8) = s1[f];
    }
    const uint4* s2 = (const uint4*)g_Wdm2;
    for (int f = tid; f < 512; f += NT) {           // 128*32/8
      int n = f >> 2, k8 = (f & 3) << 3;
      *(uint4*)(Wdm2_s + n * 40 + k8) = s2[f];
    }
    const float4* d1 = (const float4*)whdw;
    const float4* d2 = (const float4*)wvdw;
    for (int f = tid; f < 160; f += NT) {
      ((float4*)whdw_s)[f] = d1[f];
      ((float4*)wvdw_s)[f] = d2[f];
    }
  }

  // ---------- Phase 1a: flat coalesced load of 4 tiles (20-float contiguous runs) ----------
  #pragma unroll 5
  for (int f = tid; f < 12800; f += NT) {
    int c = f / 100, r = f - c * 100;
    int u = r / 20, j = r - u * 20;
    xt[c * SX + u * 20 + j] = x[base0 + c * 102400 + u * 320 + j];
  }
  // zero A pad rows (100..127)
  {
    unsigned* A32 = (unsigned*)(A + 100 * SA);
    for (int f = tid; f < 28 * (SA / 2); f += NT) A32[f] = 0u;
  }
  __syncthreads();

  // ---------- Phase 1b: depthwise conv + lrelu -> A (one (tile,channel) per thread) ----------
  {
    int i = tid >> 7, c = tid & 127;
    float xr[25];
    const float* xp = xt + c * SX + i * 5;   // xr[u*5+v] = xp[u*20 + v]
    #pragma unroll
    for (int u = 0; u < 5; ++u)
      #pragma unroll
      for (int v = 0; v < 5; ++v) xr[u * 5 + v] = xp[u * 20 + v];
    float wh[5], wv[5];
    #pragma unroll
    for (int j = 0; j < 5; ++j) { wh[j] = whdw_s[c * 5 + j]; wv[j] = wvdw_s[c * 5 + j]; }
    bf16* Ar = A + (i * 25) * SA + c;
    #pragma unroll
    for (int u = 0; u < 5; ++u) {
      #pragma unroll
      for (int v = 0; v < 5; ++v) {
        float ah = wh[2] * xr[u * 5 + v];
        float av = wv[2] * xr[u * 5 + v];
        if (v >= 1) ah += wh[1] * xr[u * 5 + v - 1];
        if (v >= 2) ah += wh[0] * xr[u * 5 + v - 2];
        if (v <= 3) ah += wh[3] * xr[u * 5 + v + 1];
        if (v <= 2) ah += wh[4] * xr[u * 5 + v + 2];
        if (u >= 1) av += wv[1] * xr[(u - 1) * 5 + v];
        if (u >= 2) av += wv[0] * xr[(u - 2) * 5 + v];
        if (u <= 3) av += wv[3] * xr[(u + 1) * 5 + v];
        if (u <= 2) av += wv[4] * xr[(u + 2) * 5 + v];
        int q = u * 5 + v;
        Ar[q * SA]       = __float2bfloat16(lrelu(ah));
        Ar[q * SA + 128] = __float2bfloat16(lrelu(av));
      }
    }
  }
  __syncthreads();

  // ---------- Phase 2: epi = A @ Wc^T   (M128 N128 K256), 16 warps 32x32 ----------
  const int wm = wid >> 2;
  const int wn = wid & 3;
  float acc[2][4][4];
  #pragma unroll
  for (int a = 0; a < 2; ++a)
    #pragma unroll
    for (int b2 = 0; b2 < 4; ++b2)
      #pragma unroll
      for (int c2 = 0; c2 < 4; ++c2) acc[a][b2][c2] = 0.f;

  #pragma unroll
  for (int kk = 0; kk < 16; ++kk) {
    int k0 = kk * 16;
    unsigned afr[2][4];
    #pragma unroll
    for (int mi = 0; mi < 2; ++mi) {
      int r = wm * 32 + mi * 16 + g;
      afr[mi][0] = *(const unsigned*)(A + r * SA + k0 + tg * 2);
      afr[mi][1] = *(const unsigned*)(A + (r + 8) * SA + k0 + tg * 2);
      afr[mi][2] = *(const unsigned*)(A + r * SA + k0 + 8 + tg * 2);
      afr[mi][3] = *(const unsigned*)(A + (r + 8) * SA + k0 + 8 + tg * 2);
    }
    #pragma unroll
    for (int ni = 0; ni < 4; ++ni) {
      int n = wn * 32 + ni * 8 + g;
      unsigned b0 = *(const unsigned*)(Wc_s + n * SA + k0 + tg * 2);
      unsigned b1 = *(const unsigned*)(Wc_s + n * SA + k0 + 8 + tg * 2);
      mma16816(acc[0][ni], afr[0], b0, b1);
      mma16816(acc[1][ni], afr[1], b0, b1);
    }
  }
  // A fully consumed; sync before overwriting region 0 with Epi
  __syncthreads();

  unsigned epk[2][4][2];
  #pragma unroll
  for (int mi = 0; mi < 2; ++mi)
    #pragma unroll
    for (int ni = 0; ni < 4; ++ni) {
      epk[mi][ni][0] = pack2(acc[mi][ni][0], acc[mi][ni][1]);
      epk[mi][ni][1] = pack2(acc[mi][ni][2], acc[mi][ni][3]);
      int r  = wm * 32 + mi * 16 + g;
      int c0 = wn * 32 + ni * 8 + tg * 2;
      *(unsigned*)(Epi + r * SE + c0)       = epk[mi][ni][0];
      *(unsigned*)(Epi + (r + 8) * SE + c0) = epk[mi][ni][1];
    }
  __syncthreads();

  // ---------- Phase 3: hid = lrelu(epi @ Wdm1^T)  (M128 N32 K128), warps 0..7 ----------
  if (wid < 8) {
    int rb = wid * 16;
    float hacc[4][4];
    #pragma unroll
    for (int a = 0; a < 4; ++a)
      #pragma unroll
      for (int b2 = 0; b2 < 4; ++b2) hacc[a][b2] = 0.f;
    #pragma unroll
    for (int kk = 0; kk < 8; ++kk) {
      int k0 = kk * 16;
      unsigned afr[4];
      int r = rb + g;
      afr[0] = *(const unsigned*)(Epi + r * SE + k0 + tg * 2);
      afr[1] = *(const unsigned*)(Epi + (r + 8) * SE + k0 + tg * 2);
      afr[2] = *(const unsigned*)(Epi + r * SE + k0 + 8 + tg * 2);
      afr[3] = *(const unsigned*)(Epi + (r + 8) * SE + k0 + 8 + tg * 2);
      #pragma unroll
      for (int ni = 0; ni < 4; ++ni) {
        int n = ni * 8 + g;
        unsigned b0 = *(const unsigned*)(Wdm1_s + n * SE + k0 + tg * 2);
        unsigned b1 = *(const unsigned*)(Wdm1_s + n * SE + k0 + 8 + tg * 2);
        mma16816(hacc[ni], afr, b0, b1);
      }
    }
    #pragma unroll
    for (int ni = 0; ni < 4; ++ni) {
      int r = rb + g, c0 = ni * 8 + tg * 2;
      *(unsigned*)(Hid + r * 40 + c0)       = pack2(lrelu(hacc[ni][0]), lrelu(hacc[ni][1]));
      *(unsigned*)(Hid + (r + 8) * 40 + c0) = pack2(lrelu(hacc[ni][2]), lrelu(hacc[ni][3]));
    }
  }
  __syncthreads();

  // ---------- Phase 4: dwgt = sigmoid(hid @ Wdm2^T); outs = scale*epi*dwgt ----------
  {
    float dacc[2][4][4];
    #pragma unroll
    for (int a = 0; a < 2; ++a)
      #pragma unroll
      for (int b2 = 0; b2 < 4; ++b2)
        #pragma unroll
        for (int c2 = 0; c2 < 4; ++c2) dacc[a][b2][c2] = 0.f;

    #pragma unroll
    for (int kk = 0; kk < 2; ++kk) {
      int k0 = kk * 16;
      unsigned afr[2][4];
      #pragma unroll
      for (int mi = 0; mi < 2; ++mi) {
        int r = wm * 32 + mi * 16 + g;
        afr[mi][0] = *(const unsigned*)(Hid + r * 40 + k0 + tg * 2);
        afr[mi][1] = *(const unsigned*)(Hid + (r + 8) * 40 + k0 + tg * 2);
        afr[mi][2] = *(const unsigned*)(Hid + r * 40 + k0 + 8 + tg * 2);
        afr[mi][3] = *(const unsigned*)(Hid + (r + 8) * 40 + k0 + 8 + tg * 2);
      }
      #pragma unroll
      for (int ni = 0; ni < 4; ++ni) {
        int n = wn * 32 + ni * 8 + g;
        unsigned b0 = *(const unsigned*)(Wdm2_s + n * 40 + k0 + tg * 2);
        unsigned b1 = *(const unsigned*)(Wdm2_s + n * 40 + k0 + 8 + tg * 2);
        mma16816(dacc[0][ni], afr[0], b0, b1);
        mma16816(dacc[1][ni], afr[1], b0, b1);
      }
    }
    float sc = scale[0];
    #pragma unroll
    for (int mi = 0; mi < 2; ++mi)
      #pragma unroll
      for (int ni = 0; ni < 4; ++ni) {
        int r  = wm * 32 + mi * 16 + g;
        int c0 = wn * 32 + ni * 8 + tg * 2;
        unsigned e01 = epk[mi][ni][0], e23 = epk[mi][ni][1];
        outs[r * SO + c0]           = sc * lo2f(e01) * sigmoidf_(dacc[mi][ni][0]);
        outs[r * SO + c0 + 1]       = sc * hi2f(e01) * sigmoidf_(dacc[mi][ni][1]);
        outs[(r + 8) * SO + c0]     = sc * lo2f(e23) * sigmoidf_(dacc[mi][ni][2]);
        outs[(r + 8) * SO + c0 + 1] = sc * hi2f(e23) * sigmoidf_(dacc[mi][ni][3]);
      }
  }
  __syncthreads();

  // ---------- Phase 5: out = xt + outs, 20-float contiguous runs, x NOT re-read ----------
  #pragma unroll 5
  for (int f = tid; f < 12800; f += NT) {
    int c = f / 100, r = f - c * 100;
    int u = r / 20, j = r - u * 20;
    int i = j / 5, v = j - i * 5;
    int row = i * 25 + u * 5 + v;
    out[base0 + c * 102400 + u * 320 + j] = xt[c * SX + u * 20 + j] + outs[row * SO + c];
  }
}

extern "C" void kernel_launch(void* const* d_in, const int* in_sizes, int n_in,
                              void* d_out, int out_size) {
  const float* x     = (const float*)d_in[0];
  const float* whdw  = (const float*)d_in[1];
  const float* whpw  = (const float*)d_in[2];
  const float* wvdw  = (const float*)d_in[3];
  const float* wvpw  = (const float*)d_in[4];
  const float* wdm1  = (const float*)d_in[5];
  const float* wdm2  = (const float*)d_in[6];
  const float* wfuse = (const float*)d_in[7];
  const float* scale = (const float*)d_in[8];
  float* out = (float*)d_out;

  prep_kernel<<<128, 128>>>(whpw, wvpw, wdm1, wdm2, wfuse);

  cudaFuncSetAttribute(epi_kernel, cudaFuncAttributeMaxDynamicSharedMemorySize, SMEM_TOTAL);
  epi_kernel<<<TILES / GRP, NT, SMEM_TOTAL>>>(x, whdw, wvdw, scale, out);
}